// round 10
// baseline (speedup 1.0000x reference)
#include <cuda_runtime.h>
#include <stdint.h>

#define BATCH 4
#define T_SEQ 2048
#define C_EMB 1024
#define NH 16
#define HD 64
#define C3 (3 * C_EMB)
#define M_ROWS (BATCH * T_SEQ)

// Scratch: __device__ globals (runtime allocation is forbidden).
__device__ float g_qkv[(size_t)M_ROWS * C3];     // [8192, 3072] (tf32-rounded)
__device__ float g_y[(size_t)M_ROWS * C_EMB];    // [8192, 1024] (tf32-rounded)
__device__ float g_xr[(size_t)M_ROWS * C_EMB];   // rounded x
__device__ float g_war[(size_t)C_EMB * C3];      // rounded W_attn
__device__ float g_wpr[(size_t)C_EMB * C_EMB];   // rounded W_proj

// ===========================================================================
// helpers
// ===========================================================================
__device__ __forceinline__ uint32_t smem_u32(const void* p) {
    uint32_t a;
    asm("{ .reg .u64 t; cvta.to.shared.u64 t, %1; cvt.u32.u64 %0, t; }"
        : "=r"(a) : "l"(p));
    return a;
}

__device__ __forceinline__ uint32_t f2tf32(float f) {
    uint32_t r;
    asm("cvt.rna.tf32.f32 %0, %1;" : "=r"(r) : "f"(f));
    return r;
}

#define CP_ASYNC16(dst_u32, src_ptr) \
    asm volatile("cp.async.cg.shared.global [%0], [%1], 16;" \
        :: "r"(dst_u32), "l"(src_ptr) : "memory")
#define CP_COMMIT() asm volatile("cp.async.commit_group;" ::: "memory")
#define CP_WAIT(n)  asm volatile("cp.async.wait_group %0;" :: "n"(n) : "memory")

__device__ __forceinline__ void mma_tf32(float* d, const uint32_t* a, const uint32_t* b) {
    asm volatile(
        "mma.sync.aligned.m16n8k8.row.col.f32.tf32.tf32.f32 "
        "{%0,%1,%2,%3}, {%4,%5,%6,%7}, {%8,%9}, {%0,%1,%2,%3};"
        : "+f"(d[0]), "+f"(d[1]), "+f"(d[2]), "+f"(d[3])
        : "r"(a[0]), "r"(a[1]), "r"(a[2]), "r"(a[3]), "r"(b[0]), "r"(b[1]));
}

// ===========================================================================
// tf32 pre-round pass
// ===========================================================================
__global__ __launch_bounds__(256) void round_tf32_kernel(
    const float4* __restrict__ src, float4* __restrict__ dst, int n4)
{
    int i = blockIdx.x * blockDim.x + threadIdx.x;
    if (i < n4) {
        float4 v = src[i];
        float4 r;
        r.x = __uint_as_float(f2tf32(v.x));
        r.y = __uint_as_float(f2tf32(v.y));
        r.z = __uint_as_float(f2tf32(v.z));
        r.w = __uint_as_float(f2tf32(v.w));
        dst[i] = r;
    }
}

// ===========================================================================
// TF32 mma.sync GEMM: C[M,N] = A[M,K] @ B[K,N] + bias[N]
// BM=256, BN=128, BK=32 -- 512 threads, 16 warps (8 along M x 2 along N),
// warp tile 32x64 (unchanged). One CTA uses the full RF (512*128 = 64K regs)
// and 16 warps/SM -> 4 warps/SMSP hide LDS->HMMA chains and the tile barrier.
// 3-stage cp.async ring, one barrier per K-tile. Operands pre-rounded tf32.
// ===========================================================================
#define BM 256
#define BN 128
#define BKT 32
#define A_STRIDE 36
#define B_STRIDE 136
#define A_BUF_FLOATS (BM * A_STRIDE)               // 9216
#define B_BUF_FLOATS (BKT * B_STRIDE)              // 4352
#define STAGE_FLOATS (A_BUF_FLOATS + B_BUF_FLOATS) // 13568
#define GEMM_SMEM_BYTES (3 * STAGE_FLOATS * 4)     // 162816

__global__ __launch_bounds__(512, 1) void gemm_tc_kernel(
    const float* __restrict__ A, const float* __restrict__ B,
    const float* __restrict__ bias, float* __restrict__ C,
    int M, int N, int K, int roundOut)
{
    extern __shared__ float sm[];
    const uint32_t sm_u = smem_u32(sm);

    const int tid  = threadIdx.x;
    const int wid  = tid >> 5;
    const int lane = tid & 31;
    const int g    = lane >> 2;
    const int tg   = lane & 3;
    const int warpM = (wid & 7) * 32;       // 8 warps along M: 0..224
    const int warpN = (wid >> 3) * 64;      // 2 warps along N: 0, 64
    const int rowBase = blockIdx.y * BM;
    const int colBase = blockIdx.x * BN;
    const int NT = K / BKT;

    // stage s occupies floats [s*STAGE_FLOATS, ...): A first, then B.
    auto issue_tile = [&](int kt, int buf) {
        const float* Ap = A + (size_t)rowBase * K + kt * BKT;
        uint32_t adst = sm_u + (uint32_t)(buf * STAGE_FLOATS) * 4;
        #pragma unroll
        for (int i = 0; i < 4; i++) {
            int f = tid + 512 * i;           // 0..2047 chunks (256 rows x 8)
            int r = f >> 3, c = f & 7;
            CP_ASYNC16(adst + (uint32_t)(r * A_STRIDE + c * 4) * 4,
                       Ap + (size_t)r * K + c * 4);
        }
        const float* Bp = B + (size_t)(kt * BKT) * N + colBase;
        uint32_t bdst = adst + (uint32_t)A_BUF_FLOATS * 4;
        #pragma unroll
        for (int i = 0; i < 2; i++) {
            int f = tid + 512 * i;           // 0..1023 chunks (32 rows x 32)
            int k = f >> 5, c = f & 31;
            CP_ASYNC16(bdst + (uint32_t)(k * B_STRIDE + c * 4) * 4,
                       Bp + (size_t)k * N + c * 4);
        }
        CP_COMMIT();
    };

    float acc[2][8][4];
    #pragma unroll
    for (int mt = 0; mt < 2; mt++)
        #pragma unroll
        for (int nt = 0; nt < 8; nt++)
            #pragma unroll
            for (int e = 0; e < 4; e++) acc[mt][nt][e] = 0.0f;

    issue_tile(0, 0);
    issue_tile(1, 1);

    int buf = 0;
    for (int kt = 0; kt < NT; kt++) {
        CP_WAIT(1);              // tile kt resident
        __syncthreads();         // all warps see it; all done computing kt-1
        if (kt + 2 < NT) {
            int nb = buf + 2; if (nb >= 3) nb -= 3;
            issue_tile(kt + 2, nb);   // buffer of tile kt-1: free after barrier
        }

        const uint32_t* Ab = (const uint32_t*)(sm + buf * STAGE_FLOATS);
        const uint32_t* Bb = Ab + A_BUF_FLOATS;

        #pragma unroll
        for (int s = 0; s < 4; s++) {
            uint32_t af[2][4], bf[8][2];
            #pragma unroll
            for (int mt = 0; mt < 2; mt++) {
                const uint32_t* ap = Ab + (warpM + mt * 16 + g) * A_STRIDE + s * 8 + tg;
                af[mt][0] = ap[0];
                af[mt][1] = ap[8 * A_STRIDE];
                af[mt][2] = ap[4];
                af[mt][3] = ap[8 * A_STRIDE + 4];
            }
            #pragma unroll
            for (int nt = 0; nt < 8; nt++) {
                const uint32_t* bp = Bb + (s * 8 + tg) * B_STRIDE + warpN + nt * 8 + g;
                bf[nt][0] = bp[0];
                bf[nt][1] = bp[4 * B_STRIDE];
            }
            #pragma unroll
            for (int mt = 0; mt < 2; mt++)
                #pragma unroll
                for (int nt = 0; nt < 8; nt++)
                    mma_tf32(acc[mt][nt], af[mt], bf[nt]);
        }

        if (++buf == 3) buf = 0;
    }

    #pragma unroll
    for (int mt = 0; mt < 2; mt++) {
        #pragma unroll
        for (int nt = 0; nt < 8; nt++) {
            int col = colBase + warpN + nt * 8 + 2 * tg;
            float2 bb = *(const float2*)&bias[col];
            int row0 = rowBase + warpM + mt * 16 + g;
            float2 v0 = { acc[mt][nt][0] + bb.x, acc[mt][nt][1] + bb.y };
            float2 v1 = { acc[mt][nt][2] + bb.x, acc[mt][nt][3] + bb.y };
            if (roundOut) {
                v0.x = __uint_as_float(f2tf32(v0.x));
                v0.y = __uint_as_float(f2tf32(v0.y));
                v1.x = __uint_as_float(f2tf32(v1.x));
                v1.y = __uint_as_float(f2tf32(v1.y));
            }
            *(float2*)&C[(size_t)row0 * N + col] = v0;
            *(float2*)&C[(size_t)(row0 + 8) * N + col] = v1;
        }
    }
}

// ===========================================================================
// Flash attention (causal) on mma.sync TF32; 2 CTAs/SM (unchanged from R9).
// ===========================================================================
#define ABR 128
#define ABC 64
#define ASTR 68
#define AK0 0
#define AV0 (ABC * ASTR)
#define AK1 (2 * ABC * ASTR)
#define AV1 (3 * ABC * ASTR)
#define APS (4 * ABC * ASTR)
#define ATTN_SMEM_FLOATS (APS + 8 * 16 * ASTR)
#define ATTN_SMEM_BYTES (ATTN_SMEM_FLOATS * 4)     // 104448

__global__ __launch_bounds__(256, 2) void attn_tc_kernel(
    const float* __restrict__ qkv, float* __restrict__ y)
{
    extern __shared__ float sm[];
    const uint32_t sm32 = smem_u32(sm);

    const int qt = (gridDim.x - 1) - blockIdx.x;
    const int h  = blockIdx.y;
    const int b  = blockIdx.z;
    const int tid  = threadIdx.x;
    const int wid  = tid >> 5;
    const int lane = tid & 31;
    const int g    = lane >> 2;
    const int tg   = lane & 3;
    const int qrow0 = qt * ABR;
    const int rw    = wid * 16;
    float* Pw = sm + APS + wid * (16 * ASTR);

    // ---- stage Q (coalesced) into P region, read A-fragments (pre-rounded)
    {
        const float* qg = qkv + (size_t)(b * T_SEQ + qrow0) * C3 + h * HD;
        #pragma unroll
        for (int i = 0; i < 8; i++) {
            int f = tid + 256 * i;
            int row = f >> 4;
            int c4  = (f & 15) << 2;
            *(float4*)&sm[APS + (row >> 4) * (16 * ASTR) + (row & 15) * ASTR + c4] =
                *(const float4*)(qg + (size_t)row * C3 + c4);
        }
    }
    __syncthreads();
    uint32_t qf[8][4];
    #pragma unroll
    for (int s = 0; s < 8; s++) {
        const uint32_t* qp = (const uint32_t*)(Pw + g * ASTR + s * 8 + tg);
        qf[s][0] = qp[0];
        qf[s][1] = qp[8 * ASTR];
        qf[s][2] = qp[4];
        qf[s][3] = qp[8 * ASTR + 4];
    }

    float o[8][4];
    #pragma unroll
    for (int nt = 0; nt < 8; nt++)
        #pragma unroll
        for (int e = 0; e < 4; e++) o[nt][e] = 0.0f;
    float m0 = -1e30f, m1 = -1e30f, l0 = 0.0f, l1 = 0.0f;
    const float scale = 0.125f;

    const int KT = 2 * qt + 2;

    auto issue = [&](int kt, int buf) {
        const float* kb = qkv + (size_t)(b * T_SEQ + kt * ABC) * C3 + C_EMB + h * HD;
        const float* vb = kb + C_EMB;
        uint32_t kdst = sm32 + (buf ? AK1 : AK0) * 4;
        uint32_t vdst = sm32 + (buf ? AV1 : AV0) * 4;
        #pragma unroll
        for (int i = 0; i < 4; i++) {
            int f = tid + 256 * i;
            int row = f >> 4, c = f & 15;
            CP_ASYNC16(kdst + (uint32_t)(row * ASTR + c * 4) * 4,
                       kb + (size_t)row * C3 + c * 4);
        }
        #pragma unroll
        for (int i = 0; i < 4; i++) {
            int f = tid + 256 * i;
            int row = f >> 4, c = f & 15;
            CP_ASYNC16(vdst + (uint32_t)(row * ASTR + c * 4) * 4,
                       vb + (size_t)row * C3 + c * 4);
        }
        CP_COMMIT();
    };

    issue(0, 0);
    for (int kt = 0; kt < KT; kt++) {
        if (kt + 1 < KT) { issue(kt + 1, (kt + 1) & 1); CP_WAIT(1); }
        else             { CP_WAIT(0); }
        __syncthreads();

        const uint32_t* Kb = (const uint32_t*)(sm + ((kt & 1) ? AK1 : AK0));
        const uint32_t* Vb = (const uint32_t*)(sm + ((kt & 1) ? AV1 : AV0));

        bool alive = (kt * ABC) <= (qrow0 + rw + 15);
        if (alive) {
            // ---- S = Q K^T
            float sa[8][4];
            #pragma unroll
            for (int nt = 0; nt < 8; nt++)
                #pragma unroll
                for (int e = 0; e < 4; e++) sa[nt][e] = 0.0f;
            #pragma unroll
            for (int s = 0; s < 8; s++) {
                #pragma unroll
                for (int nt = 0; nt < 8; nt++) {
                    uint32_t bf[2];
                    const uint32_t* kp = Kb + (nt * 8 + g) * ASTR + s * 8 + tg;
                    bf[0] = kp[0];
                    bf[1] = kp[4];
                    mma_tf32(sa[nt], qf[s], bf);
                }
            }

            // ---- mask + online softmax
            bool band = (kt * ABC + ABC - 1) > (qrow0 + rw);
            int grow0 = qrow0 + rw + g;
            int gcol0 = kt * ABC + 2 * tg;
            float mx0 = m0, mx1 = m1;
            #pragma unroll
            for (int nt = 0; nt < 8; nt++) {
                int c0 = gcol0 + nt * 8;
                float v0 = sa[nt][0] * scale;
                float v1 = sa[nt][1] * scale;
                float v2 = sa[nt][2] * scale;
                float v3 = sa[nt][3] * scale;
                if (band) {
                    if (c0     > grow0)     v0 = -1e30f;
                    if (c0 + 1 > grow0)     v1 = -1e30f;
                    if (c0     > grow0 + 8) v2 = -1e30f;
                    if (c0 + 1 > grow0 + 8) v3 = -1e30f;
                }
                sa[nt][0] = v0; sa[nt][1] = v1; sa[nt][2] = v2; sa[nt][3] = v3;
                mx0 = fmaxf(mx0, fmaxf(v0, v1));
                mx1 = fmaxf(mx1, fmaxf(v2, v3));
            }
            mx0 = fmaxf(mx0, __shfl_xor_sync(0xffffffffu, mx0, 1));
            mx0 = fmaxf(mx0, __shfl_xor_sync(0xffffffffu, mx0, 2));
            mx1 = fmaxf(mx1, __shfl_xor_sync(0xffffffffu, mx1, 1));
            mx1 = fmaxf(mx1, __shfl_xor_sync(0xffffffffu, mx1, 2));
            float corr0 = __expf(m0 - mx0);
            float corr1 = __expf(m1 - mx1);
            m0 = mx0; m1 = mx1;

            float ls0 = 0.0f, ls1 = 0.0f;
            #pragma unroll
            for (int nt = 0; nt < 8; nt++) {
                float p0 = __expf(sa[nt][0] - m0);
                float p1 = __expf(sa[nt][1] - m0);
                float p2 = __expf(sa[nt][2] - m1);
                float p3 = __expf(sa[nt][3] - m1);
                sa[nt][0] = p0; sa[nt][1] = p1; sa[nt][2] = p2; sa[nt][3] = p3;
                ls0 += p0 + p1;
                ls1 += p2 + p3;
            }
            l0 = l0 * corr0 + ls0;
            l1 = l1 * corr1 + ls1;
            #pragma unroll
            for (int nt = 0; nt < 8; nt++) {
                o[nt][0] *= corr0; o[nt][1] *= corr0;
                o[nt][2] *= corr1; o[nt][3] *= corr1;
            }

            // ---- P -> smem (warp-private), reread as A-fragments (CVT here)
            __syncwarp();
            #pragma unroll
            for (int nt = 0; nt < 8; nt++) {
                *(float2*)&Pw[g * ASTR + nt * 8 + 2 * tg]       = *(float2*)&sa[nt][0];
                *(float2*)&Pw[(g + 8) * ASTR + nt * 8 + 2 * tg] = *(float2*)&sa[nt][2];
            }
            __syncwarp();

            // ---- O += P V
            #pragma unroll
            for (int s = 0; s < 8; s++) {
                uint32_t pf[4];
                const float* pp = Pw + g * ASTR + s * 8 + tg;
                pf[0] = f2tf32(pp[0]);
                pf[1] = f2tf32(pp[8 * ASTR]);
                pf[2] = f2tf32(pp[4]);
                pf[3] = f2tf32(pp[8 * ASTR + 4]);
                #pragma unroll
                for (int nt = 0; nt < 8; nt++) {
                    uint32_t bf[2];
                    const uint32_t* vp = Vb + (s * 8 + tg) * ASTR + nt * 8 + g;
                    bf[0] = vp[0];
                    bf[1] = vp[4 * ASTR];
                    mma_tf32(o[nt], pf, bf);
                }
            }
        }
        __syncthreads();
    }

    // ---- final l reduction + normalize + write (tf32-rounded for proj GEMM)
    l0 += __shfl_xor_sync(0xffffffffu, l0, 1);
    l0 += __shfl_xor_sync(0xffffffffu, l0, 2);
    l1 += __shfl_xor_sync(0xffffffffu, l1, 1);
    l1 += __shfl_xor_sync(0xffffffffu, l1, 2);
    float inv0 = 1.0f / l0;
    float inv1 = 1.0f / l1;

    int row0 = b * T_SEQ + qrow0 + rw + g;
    #pragma unroll
    for (int nt = 0; nt < 8; nt++) {
        int col = h * HD + nt * 8 + 2 * tg;
        float2 v0 = { __uint_as_float(f2tf32(o[nt][0] * inv0)),
                      __uint_as_float(f2tf32(o[nt][1] * inv0)) };
        float2 v1 = { __uint_as_float(f2tf32(o[nt][2] * inv1)),
                      __uint_as_float(f2tf32(o[nt][3] * inv1)) };
        *(float2*)&y[(size_t)row0 * C_EMB + col] = v0;
        *(float2*)&y[(size_t)(row0 + 8) * C_EMB + col] = v1;
    }
}

// ===========================================================================
extern "C" void kernel_launch(void* const* d_in, const int* in_sizes, int n_in,
                              void* d_out, int out_size)
{
    const float* x      = (const float*)d_in[0];
    const float* W_attn = (const float*)d_in[1];
    const float* b_attn = (const float*)d_in[2];
    const float* W_proj = (const float*)d_in[3];
    const float* b_proj = (const float*)d_in[4];
    float* out = (float*)d_out;

    float *qkv, *yb, *xr, *war, *wpr;
    cudaGetSymbolAddress((void**)&qkv, g_qkv);
    cudaGetSymbolAddress((void**)&yb,  g_y);
    cudaGetSymbolAddress((void**)&xr,  g_xr);
    cudaGetSymbolAddress((void**)&war, g_war);
    cudaGetSymbolAddress((void**)&wpr, g_wpr);

    cudaFuncSetAttribute(gemm_tc_kernel,
                         cudaFuncAttributeMaxDynamicSharedMemorySize, GEMM_SMEM_BYTES);
    cudaFuncSetAttribute(attn_tc_kernel,
                         cudaFuncAttributeMaxDynamicSharedMemorySize, ATTN_SMEM_BYTES);

    // 0) pre-round inputs to tf32 (once; hot loops then run CVT-free)
    {
        int n4x = (M_ROWS * C_EMB) / 4;
        int n4a = (C_EMB * C3) / 4;
        int n4p = (C_EMB * C_EMB) / 4;
        round_tf32_kernel<<<n4x / 256, 256>>>((const float4*)x, (float4*)xr, n4x);
        round_tf32_kernel<<<n4a / 256, 256>>>((const float4*)W_attn, (float4*)war, n4a);
        round_tf32_kernel<<<n4p / 256, 256>>>((const float4*)W_proj, (float4*)wpr, n4p);
    }

    // 1) qkv = x_r @ Wa_r + b_attn  (epilogue writes tf32-rounded qkv)
    gemm_tc_kernel<<<dim3(C3 / BN, M_ROWS / BM), 512, GEMM_SMEM_BYTES>>>(
        xr, war, b_attn, qkv, M_ROWS, C3, C_EMB, 1);

    // 2) causal flash attention -> y (tf32-rounded)
    attn_tc_kernel<<<dim3(T_SEQ / ABR, NH, BATCH), 256, ATTN_SMEM_BYTES>>>(qkv, yb);

    // 3) out = y @ Wp_r + b_proj  (final output: NOT rounded)
    gemm_tc_kernel<<<dim3(C_EMB / BN, M_ROWS / BM), 512, GEMM_SMEM_BYTES>>>(
        yb, wpr, b_proj, out, M_ROWS, C_EMB, C_EMB, 0);
}